// round 7
// baseline (speedup 1.0000x reference)
#include <cuda_runtime.h>
#include <cuda_bf16.h>
#include <math.h>

// Problem constants
#define BB   4
#define LL   2048
#define DD   1024
#define KK   16
#define BL   (BB*LL)        // 8192 tokens
#define NCH  32             // scan chunks
#define LC   (LL/NCH)       // 64 tokens per chunk

// ---------------------------------------------------------------------------
// Scratch (no allocation allowed -> __device__ globals)
// ---------------------------------------------------------------------------
__device__ float g_value[BL*DD];            // 32 MB
__device__ float g_ret  [BL*DD];            // 32 MB (retrieved, pre-LN)
__device__ float g_ck   [BL*KK];
__device__ float g_cq   [BL*KK];
__device__ float g_S    [BB*NCH*KK*DD];     // 8 MB chunk states

// bf16 hi/lo operand panels, chunk-major, swizzled (cell ^ (row&7)) layout.
__device__ uint4 g_ahi[(16*8192*128)/16];   // 16 MB
__device__ uint4 g_alo[(16*8192*128)/16];   // 16 MB
__device__ uint4 g_bhi[(16*1024*128)/16];   // 2 MB  (Wv)
__device__ uint4 g_blo[(16*1024*128)/16];   // 2 MB
__device__ uint4 g_bhi2[(16*1024*128)/16];  // 2 MB  (Wo)
__device__ uint4 g_blo2[(16*1024*128)/16];  // 2 MB

// ---------------------------------------------------------------------------
// PTX helpers (base sm_90/sm_80 features only — target is plain sm_100!)
// ---------------------------------------------------------------------------
__device__ __forceinline__ unsigned smem_u32(const void* p) {
    unsigned a;
    asm("{ .reg .u64 t; cvta.to.shared.u64 t, %1; cvt.u32.u64 %0, t; }" : "=r"(a) : "l"(p));
    return a;
}

#define MBAR_INIT(addr, cnt) \
    asm volatile("mbarrier.init.shared.b64 [%0], %1;" :: "r"(addr), "r"(cnt) : "memory")
#define MBAR_INVAL(addr) \
    asm volatile("mbarrier.inval.shared.b64 [%0];" :: "r"(addr) : "memory")
#define MBAR_EXPECT_TX(addr, bytes) \
    asm volatile("mbarrier.arrive.expect_tx.shared.b64 _, [%0], %1;" :: "r"(addr), "r"(bytes) : "memory")
#define MBAR_ARRIVE(addr) \
    asm volatile("mbarrier.arrive.shared.b64 _, [%0];" :: "r"(addr) : "memory")

#define MBAR_WAIT(addr, par) do {                                              \
    unsigned _m = (addr), _p = (par), _d;                                      \
    asm volatile("{\n\t.reg .pred p;\n\t"                                      \
        "mbarrier.try_wait.parity.acquire.cta.shared::cta.b64 p, [%1], %2;\n\t"\
        "selp.b32 %0, 1, 0, p;\n\t}"                                           \
        : "=r"(_d) : "r"(_m), "r"(_p) : "memory");                             \
    if (!_d) {                                                                 \
        asm volatile("{\n\t.reg .pred P1;\n\t"                                 \
            "W%=:\n\t"                                                         \
            "mbarrier.try_wait.parity.acquire.cta.shared::cta.b64 P1, [%0], %1, 0x989680;\n\t" \
            "@P1 bra.uni D%=;\n\t"                                             \
            "bra.uni W%=;\n\t"                                                 \
            "D%=:\n\t}" :: "r"(_m), "r"(_p) : "memory");                       \
    }                                                                          \
} while (0)

#define CP_BULK(dst, src, bytes, mbar) \
    asm volatile("cp.async.bulk.shared::cluster.global.mbarrier::complete_tx::bytes [%0], [%1], %2, [%3];" \
        :: "r"(dst), "l"(src), "r"(bytes), "r"(mbar) : "memory")

#define FENCE_PROXY() asm volatile("fence.proxy.async.shared::cta;" ::: "memory")

#define LDSM_X4(r0, r1, r2, r3, addr) \
    asm volatile("ldmatrix.sync.aligned.m8n8.x4.shared.b16 {%0,%1,%2,%3}, [%4];" \
        : "=r"(r0), "=r"(r1), "=r"(r2), "=r"(r3) : "r"(addr))

__device__ __forceinline__ void mma16816(float* d, const unsigned* a, const unsigned* b) {
    asm volatile("mma.sync.aligned.m16n8k16.row.col.f32.bf16.bf16.f32 "
        "{%0,%1,%2,%3}, {%4,%5,%6,%7}, {%8,%9}, {%0,%1,%2,%3};"
        : "+f"(d[0]), "+f"(d[1]), "+f"(d[2]), "+f"(d[3])
        : "r"(a[0]), "r"(a[1]), "r"(a[2]), "r"(a[3]), "r"(b[0]), "r"(b[1]));
}

// pack 2 floats -> bf16x2 bits (lo = first arg)
__device__ __forceinline__ unsigned pk2(float x, float y) {
    __nv_bfloat162 h = __floats2bfloat162_rn(x, y);
    return *reinterpret_cast<unsigned*>(&h);
}

// ---------------------------------------------------------------------------
// Kernel: conv_w — W (1024x1024 fp32) -> B panels (P=0: Wv, P=1: Wo)
// ---------------------------------------------------------------------------
template<int P>
__global__ __launch_bounds__(256)
void conv_w(const float* __restrict__ src)
{
    int id = blockIdx.x * 256 + threadIdx.x;     // 0 .. 1024*128-1
    int n = id >> 7;
    int cc = id & 127;
    int c = cc >> 3, cell = cc & 7;
    int k0 = c * 64 + cell * 8;

    const float4* s = (const float4*)(src + (size_t)n * DD + k0);
    float4 a = s[0], b = s[1];

    float v[8] = {a.x, a.y, a.z, a.w, b.x, b.y, b.z, b.w};
    float hi[8], lo[8];
    #pragma unroll
    for (int i = 0; i < 8; ++i) {
        __nv_bfloat16 h = __float2bfloat16_rn(v[i]);
        hi[i] = __bfloat162float(h);
        lo[i] = v[i] - hi[i];
    }
    uint4 H  = make_uint4(pk2(hi[0],hi[1]), pk2(hi[2],hi[3]), pk2(hi[4],hi[5]), pk2(hi[6],hi[7]));
    uint4 Lo = make_uint4(pk2(lo[0],lo[1]), pk2(lo[2],lo[3]), pk2(lo[4],lo[5]), pk2(lo[6],lo[7]));

    size_t off16 = ((size_t)c * DD + n) * 8 + (cell ^ (n & 7));
    if (P == 0) { g_bhi[off16]  = H; g_blo[off16]  = Lo; }
    else        { g_bhi2[off16] = H; g_blo2[off16] = Lo; }
}

// ---------------------------------------------------------------------------
// Kernel: mma_gemm — C[8192x1024] = A @ W^T (+bias, optionally +X residual)
// 3-stage cp.async.bulk pipeline, scoped mbarrier flow control,
// register double-buffered ldmatrix, 3-pass mma issue (dependency spacing).
// CTA tile 128x128, 16 warps (4x4), warp tile 32x32.
// MODE 0: C = g_value, B = Wv panels. MODE 1: C = Cout += X, B = Wo panels.
// ---------------------------------------------------------------------------
#define TILE_B  16384                   // one 128x64 bf16 tile
#define STG     (4*TILE_B)              // Ah, Al, Bh, Bl = 64 KB
#define KBLK    16
#define NSTAGE  3
#define GSMEM   (1024 + NSTAGE*STG)     // 197632

template<int MODE>
__global__ __launch_bounds__(512, 1)
void mma_gemm(const float* __restrict__ bias, const float* __restrict__ X,
              float* __restrict__ Cout)
{
    extern __shared__ char smem[];
    unsigned sb = smem_u32(smem);
    int tid = threadIdx.x, lane = tid & 31, wid = tid >> 5;
    int wm = wid & 3, wn = wid >> 2;          // 4 x 4 warp grid, 32x32 tiles
    int bn = blockIdx.x * 128, bm = blockIdx.y * 128;
    float* C = (MODE == 0) ? g_value : Cout;

    // mbarriers: full[s] at sb+8+16s, cons[s] at sb+16+16s
    if (tid == 0) {
        #pragma unroll
        for (int s = 0; s < NSTAGE; ++s) {
            MBAR_INIT(sb + 8  + 16*s, 1);
            MBAR_INIT(sb + 16 + 16*s, 16);
        }
        FENCE_PROXY();
    }
    __syncthreads();

    const char* pAh = (const char*)g_ahi;
    const char* pAl = (const char*)g_alo;
    const char* pBh = (MODE == 0) ? (const char*)g_bhi : (const char*)g_bhi2;
    const char* pBl = (MODE == 0) ? (const char*)g_blo : (const char*)g_blo2;

    auto issue = [&](int kb, int s) {
        unsigned st = sb + 1024 + s * STG;
        unsigned fm = sb + 8 + 16*s;
        size_t aoff = ((size_t)kb * BL + bm) * 128;
        size_t boff = ((size_t)kb * DD + bn) * 128;
        MBAR_EXPECT_TX(fm, STG);
        CP_BULK(st,            pAh + aoff, TILE_B, fm);
        CP_BULK(st +   TILE_B, pAl + aoff, TILE_B, fm);
        CP_BULK(st + 2*TILE_B, pBh + boff, TILE_B, fm);
        CP_BULK(st + 3*TILE_B, pBl + boff, TILE_B, fm);
    };
    if (tid == 0) { issue(0, 0); issue(1, 1); issue(2, 2); }

    float acc[2][4][4];
    #pragma unroll
    for (int i = 0; i < 2; ++i)
        #pragma unroll
        for (int j = 0; j < 4; ++j)
            #pragma unroll
            for (int q = 0; q < 4; ++q) acc[i][j][q] = 0.f;

    int rl = (lane & 7) + ((lane >> 3) & 1) * 8;
    int cs = lane >> 4;

    int rA[2], sA[2], rB[2], sB[2];
    #pragma unroll
    for (int i = 0; i < 2; ++i) { int r = wm*32 + i*16 + rl; rA[i] = r*128; sA[i] = r & 7; }
    #pragma unroll
    for (int j = 0; j < 2; ++j) { int r = wn*32 + j*16 + rl; rB[j] = r*128; sB[j] = r & 7; }

    // operand double buffers
    unsigned opA[2][16], opB[2][16];

    auto load_ops = [&](unsigned bAh, unsigned bAl, unsigned bBh, unsigned bBl,
                        int ks, unsigned* A, unsigned* B) {
        int cc = ks * 2 + cs;
        #pragma unroll
        for (int i = 0; i < 2; ++i) {
            unsigned off = rA[i] + ((cc ^ sA[i]) << 4);
            LDSM_X4(A[i*4+0], A[i*4+1], A[i*4+2], A[i*4+3], bAh + off);
            LDSM_X4(A[8+i*4+0], A[8+i*4+1], A[8+i*4+2], A[8+i*4+3], bAl + off);
        }
        #pragma unroll
        for (int jp = 0; jp < 2; ++jp) {
            unsigned off = rB[jp] + ((cc ^ sB[jp]) << 4);
            unsigned r0, r1, r2, r3;
            LDSM_X4(r0, r1, r2, r3, bBh + off);
            B[jp*8+0] = r0; B[jp*8+1] = r2; B[jp*8+2] = r1; B[jp*8+3] = r3;
            LDSM_X4(r0, r1, r2, r3, bBl + off);
            B[jp*8+4] = r0; B[jp*8+5] = r2; B[jp*8+6] = r1; B[jp*8+7] = r3;
        }
    };

    // 3-pass issue: 8 independent mmas between any accumulator reuse
    auto do_mma = [&](const unsigned* A, const unsigned* B) {
        #pragma unroll
        for (int jp = 0; jp < 2; ++jp)       // pass 1: hi*hi
            #pragma unroll
            for (int i = 0; i < 2; ++i) {
                mma16816(acc[i][jp*2+0], A + i*4, B + jp*8 + 0);
                mma16816(acc[i][jp*2+1], A + i*4, B + jp*8 + 2);
            }
        #pragma unroll
        for (int jp = 0; jp < 2; ++jp)       // pass 2: lo*hi
            #pragma unroll
            for (int i = 0; i < 2; ++i) {
                mma16816(acc[i][jp*2+0], A + 8 + i*4, B + jp*8 + 0);
                mma16816(acc[i][jp*2+1], A + 8 + i*4, B + jp*8 + 2);
            }
        #pragma unroll
        for (int jp = 0; jp < 2; ++jp)       // pass 3: hi*lo
            #pragma unroll
            for (int i = 0; i < 2; ++i) {
                mma16816(acc[i][jp*2+0], A + i*4, B + jp*8 + 4);
                mma16816(acc[i][jp*2+1], A + i*4, B + jp*8 + 6);
            }
    };

    for (int kb = 0; kb < KBLK; ++kb) {
        int s  = kb % NSTAGE;
        int ph = (kb / NSTAGE) & 1;
        MBAR_WAIT(sb + 8 + 16*s, ph);
        unsigned st  = sb + 1024 + s * STG;
        unsigned bAh = st, bAl = st + TILE_B, bBh = st + 2*TILE_B, bBl = st + 3*TILE_B;

        load_ops(bAh, bAl, bBh, bBl, 0, opA[0], opB[0]);
        #pragma unroll
        for (int ks = 0; ks < 4; ++ks) {
            int cur = ks & 1;
            if (ks < 3) load_ops(bAh, bAl, bBh, bBl, ks + 1, opA[cur^1], opB[cur^1]);
            do_mma(opA[cur], opB[cur]);
        }

        if (lane == 0) MBAR_ARRIVE(sb + 16 + 16*s);
        if (tid == 0 && kb + NSTAGE < KBLK) {
            MBAR_WAIT(sb + 16 + 16*s, ph);
            issue(kb + NSTAGE, s);
        }
    }

    // epilogue: warp writes its 32x32 sub-tile
    #pragma unroll
    for (int i = 0; i < 2; ++i) {
        int r0 = bm + wm*32 + i*16 + (lane >> 2);
        #pragma unroll
        for (int j = 0; j < 4; ++j) {
            int col = bn + wn*32 + j*8 + (lane & 3)*2;
            float2 b2 = *(const float2*)(bias + col);
            float2 v0 = make_float2(acc[i][j][0] + b2.x, acc[i][j][1] + b2.y);
            float2 v1 = make_float2(acc[i][j][2] + b2.x, acc[i][j][3] + b2.y);
            if (MODE == 1) {
                float2 x0 = *(const float2*)(X + (size_t)r0*DD + col);
                float2 x1 = *(const float2*)(X + (size_t)(r0+8)*DD + col);
                v0.x += x0.x; v0.y += x0.y;
                v1.x += x1.x; v1.y += x1.y;
            }
            *(float2*)(C + (size_t)r0*DD + col)     = v0;
            *(float2*)(C + (size_t)(r0+8)*DD + col) = v1;
        }
    }

    __syncthreads();
    if (tid == 0) {
        #pragma unroll
        for (int s = 0; s < NSTAGE; ++s) {
            MBAR_INVAL(sb + 8  + 16*s);
            MBAR_INVAL(sb + 16 + 16*s);
        }
    }
}

// ---------------------------------------------------------------------------
// Kernel: proj — content key/query + combiner for 8 tokens per block,
// FUSED with x -> bf16 hi/lo A-panel conversion (reads x once).
// 1024 blocks x 256 threads.
// ---------------------------------------------------------------------------
#define PT 8
__global__ __launch_bounds__(256)
void proj_kernel(const float* __restrict__ x,
                 const float* __restrict__ Wck, const float* __restrict__ bck,
                 const float* __restrict__ Wcq, const float* __restrict__ bcq,
                 const float* __restrict__ Wc,  const float* __restrict__ bc,
                 const float* __restrict__ pos_key)
{
    int t0   = blockIdx.x * PT;
    int tid  = threadIdx.x;
    int lane = tid & 31;
    int warp = tid >> 5;

    __shared__ float xs[PT][DD];
    __shared__ float dots[2][PT][16];
    __shared__ float pos_s[PT][16];

    #pragma unroll
    for (int i = tid; i < PT*DD/4; i += 256)
        ((float4*)&xs[0][0])[i] = ((const float4*)(x + (size_t)t0*DD))[i];
    if (tid < PT*16) {
        int tt = tid >> 4, k = tid & 15;
        int l = (t0 + tt) & (LL-1);
        pos_s[tt][k] = pos_key[l*KK + k];
    }
    __syncthreads();

    // --- fused conv_act: emit hi/lo panels for these 8 rows ---
    {
        int tt   = tid >> 5;              // row within block (0..7)
        int t    = t0 + tt;
        int cell = lane & 7;              // 16B cell within 64-elem chunk row
        #pragma unroll
        for (int q = 0; q < 4; ++q) {
            int c  = (lane >> 3) + q*4;   // chunk 0..15
            int k0 = c*64 + cell*8;
            float hi[8], lo[8];
            #pragma unroll
            for (int i = 0; i < 8; ++i) {
                float v = xs[tt][k0 + i];
                __nv_bfloat16 h = __float2bfloat16_rn(v);
                hi[i] = __bfloat162float(h);
                lo[i] = v - hi[i];
            }
            uint4 H  = make_uint4(pk2(hi[0],hi[1]), pk2(hi[2],hi[3]), pk2(hi[4],hi[5]), pk2(hi[6],hi[7]));
            uint4 Lo = make_uint4(pk2(lo[0],lo[1]), pk2(lo[2],lo[3]), pk2(lo[4],lo[5]), pk2(lo[6],lo[7]));
            size_t off16 = ((size_t)c * BL + t) * 8 + (cell ^ (t & 7));
            g_ahi[off16] = H;
            g_alo[off16] = Lo;
        }
    }

    // --- 32 dot products; each warp does 4 (sequential — keeps regs low) ---
    #pragma unroll 1
    for (int oo = 0; oo < 4; ++oo) {
        int o = warp + oo*8;
        const float* W = (o < 16) ? (Wck + (size_t)o*DD) : (Wcq + (size_t)(o-16)*DD);
        float bias_o   = (o < 16) ? bck[o] : bcq[o-16];
        float wreg[32];
        #pragma unroll
        for (int i = 0; i < 32; ++i) wreg[i] = W[lane + 32*i];
        #pragma unroll
        for (int t = 0; t < PT; ++t) {
            float s = 0.f;
            #pragma unroll
            for (int i = 0; i < 32; ++i) s += wreg[i] * xs[t][lane + 32*i];
            #pragma unroll
            for (int off = 16; off; off >>= 1)
                s += __shfl_xor_sync(0xffffffffu, s, off);
            if (lane == 0)
                dots[o >> 4][t][o & 15] = s + bias_o;
        }
    }
    __syncthreads();

    // --- normalize + combiner + normalize ---
    {
        int t    = warp;
        int path = lane >> 4;
        int l16  = lane & 15;

        float v = dots[path][t][l16];
        float ss = v*v;
        #pragma unroll
        for (int off = 8; off; off >>= 1)
            ss += __shfl_xor_sync(0xffffffffu, ss, off, 16);
        float cnv = v / fmaxf(sqrtf(ss), 1e-12f);

        float s = bc[l16];
        #pragma unroll
        for (int j = 0; j < 16; ++j) {
            float cj = __shfl_sync(0xffffffffu, cnv, j, 16);
            s += Wc[l16*32 + j]      * pos_s[t][j];
            s += Wc[l16*32 + 16 + j] * cj;
        }
        s = tanhf(s);
        float sq = s*s;
        #pragma unroll
        for (int off = 8; off; off >>= 1)
            sq += __shfl_xor_sync(0xffffffffu, sq, off, 16);
        float outv = s / fmaxf(sqrtf(sq), 1e-12f);
        float* dst = (path == 0) ? g_ck : g_cq;
        dst[(t0 + t)*KK + l16] = outv;
    }
}

// ---------------------------------------------------------------------------
// Kernel: per-chunk partial state  S[b,c,k,d] = sum_{t in chunk} v[t,d]*ck[t,k]
// ---------------------------------------------------------------------------
__global__ __launch_bounds__(128)
void scan_partial()
{
    int d = blockIdx.x * 128 + threadIdx.x;
    int c = blockIdx.y;
    int b = blockIdx.z;
    __shared__ float cks[LC*KK];

    int base_t = b*LL + c*LC;
    for (int i = threadIdx.x; i < LC*KK; i += 128)
        cks[i] = g_ck[base_t*KK + i];
    __syncthreads();

    float st[KK];
    #pragma unroll
    for (int k = 0; k < KK; ++k) st[k] = 0.f;

    const float* vp = g_value + (size_t)base_t*DD + d;
    for (int t = 0; t < LC; ++t) {
        float v = vp[(size_t)t*DD];
        #pragma unroll
        for (int k = 0; k < KK; ++k) st[k] += v * cks[t*KK + k];
    }
    float* Sp = g_S + ((size_t)(b*NCH + c)*KK)*DD + d;
    #pragma unroll
    for (int k = 0; k < KK; ++k) Sp[(size_t)k*DD] = st[k];
}

// ---------------------------------------------------------------------------
// Kernel: exclusive prefix over chunks — batched loads for MLP
// ---------------------------------------------------------------------------
__global__ __launch_bounds__(256)
void scan_prefix()
{
    int id  = blockIdx.x * 256 + threadIdx.x;   // 0 .. B*K*D-1
    int b   = id >> 14;
    int rem = id & 16383;
    float* base = g_S + (size_t)b*NCH*KK*DD + rem;

    float v[NCH];
    #pragma unroll
    for (int c = 0; c < NCH; ++c)
        v[c] = base[(size_t)c*KK*DD];
    float run = 0.f;
    #pragma unroll
    for (int c = 0; c < NCH; ++c) {
        float t = v[c];
        base[(size_t)c*KK*DD] = run;
        run += t;
    }
}

// ---------------------------------------------------------------------------
// Kernel: apply scan within chunk -> retrieved (scaled 1/sqrt K) into g_ret
// ---------------------------------------------------------------------------
__global__ __launch_bounds__(128)
void scan_apply()
{
    int d = blockIdx.x * 128 + threadIdx.x;
    int c = blockIdx.y;
    int b = blockIdx.z;
    __shared__ float cks[LC*KK];
    __shared__ float cqs[LC*KK];

    int base_t = b*LL + c*LC;
    for (int i = threadIdx.x; i < LC*KK; i += 128) {
        cks[i] = g_ck[base_t*KK + i];
        cqs[i] = g_cq[base_t*KK + i];
    }
    __syncthreads();

    float st[KK];
    const float* Sp = g_S + ((size_t)(b*NCH + c)*KK)*DD + d;
    #pragma unroll
    for (int k = 0; k < KK; ++k) st[k] = Sp[(size_t)k*DD];

    const float* vp = g_value + (size_t)base_t*DD + d;
    float*       rp = g_ret   + (size_t)base_t*DD + d;
    for (int t = 0; t < LC; ++t) {
        float v = vp[(size_t)t*DD];
        float acc = 0.f;
        #pragma unroll
        for (int k = 0; k < KK; ++k) {
            st[k] += v * cks[t*KK + k];
            acc   += cqs[t*KK + k] * st[k];
        }
        rp[(size_t)t*DD] = acc * 0.25f;
    }
}

// ---------------------------------------------------------------------------
// Kernel: LayerNorm on g_ret, fused bf16 hi/lo panel output (for mma_gemm<1>)
// ---------------------------------------------------------------------------
__global__ __launch_bounds__(256)
void layernorm_conv(const float* __restrict__ gam, const float* __restrict__ bet)
{
    int t = blockIdx.x;
    const float* row = g_ret + (size_t)t*DD;
    __shared__ float sh[DD];
    __shared__ float ws[8], wq[8];
    __shared__ float s_mean, s_rstd;

    int tid  = threadIdx.x;
    int lane = tid & 31;
    int wid  = tid >> 5;

    float4 v = ((const float4*)row)[tid];
    ((float4*)sh)[tid] = v;
    float s = v.x + v.y + v.z + v.w;
    float q = v.x*v.x + v.y*v.y + v.z*v.z + v.w*v.w;
    #pragma unroll
    for (int off = 16; off; off >>= 1) {
        s += __shfl_xor_sync(0xffffffffu, s, off);
        q += __shfl_xor_sync(0xffffffffu, q, off);
    }
    if (lane == 0) { ws[wid] = s; wq[wid] = q; }
    __syncthreads();
    if (tid == 0) {
        float S = 0.f, Q = 0.f;
        #pragma unroll
        for (int i = 0; i < 8; ++i) { S += ws[i]; Q += wq[i]; }
        float m   = S / (float)DD;
        float var = Q / (float)DD - m*m;
        s_mean = m;
        s_rstd = rsqrtf(var + 1e-5f);
    }
    __syncthreads();
    float m = s_mean, r = s_rstd;

    int d0 = tid * 4;
    float nv[4], hi[4], lo[4];
    #pragma unroll
    for (int i = 0; i < 4; ++i) {
        int d = d0 + i;
        nv[i] = (sh[d] - m) * r * gam[d] + bet[d];
        __nv_bfloat16 h = __float2bfloat16_rn(nv[i]);
        hi[i] = __bfloat162float(h);
        lo[i] = nv[i] - hi[i];
    }
    int c8    = d0 >> 6;
    int inrow = ((d0 & 63) * 2) ^ ((t & 7) << 4);
    size_t byteoff = ((size_t)c8 * BL + t) * 128 + inrow;
    *(uint2*)((char*)g_ahi + byteoff) = make_uint2(pk2(hi[0],hi[1]), pk2(hi[2],hi[3]));
    *(uint2*)((char*)g_alo + byteoff) = make_uint2(pk2(lo[0],lo[1]), pk2(lo[2],lo[3]));
}

// ---------------------------------------------------------------------------
extern "C" void kernel_launch(void* const* d_in, const int* in_sizes, int n_in,
                              void* d_out, int out_size)
{
    const float* x       = (const float*)d_in[0];
    const float* Wv      = (const float*)d_in[1];
    const float* bv      = (const float*)d_in[2];
    const float* Wck     = (const float*)d_in[3];
    const float* bck     = (const float*)d_in[4];
    const float* Wc      = (const float*)d_in[5];
    const float* bc      = (const float*)d_in[6];
    const float* Wcq     = (const float*)d_in[7];
    const float* bcq     = (const float*)d_in[8];
    const float* ln_g    = (const float*)d_in[9];
    const float* ln_b    = (const float*)d_in[10];
    const float* Wo      = (const float*)d_in[11];
    const float* bo      = (const float*)d_in[12];
    const float* pos_key = (const float*)d_in[13];
    float* out = (float*)d_out;

    cudaFuncSetAttribute(mma_gemm<0>, cudaFuncAttributeMaxDynamicSharedMemorySize, GSMEM);
    cudaFuncSetAttribute(mma_gemm<1>, cudaFuncAttributeMaxDynamicSharedMemorySize, GSMEM);

    // weight panels (off critical path)
    conv_w<0><<<(DD*128)/256, 256>>>(Wv);
    conv_w<1><<<(DD*128)/256, 256>>>(Wo);

    // proj + fused x->panel conversion
    proj_kernel<<<BL/PT, 256>>>(x, Wck, bck, Wcq, bcq, Wc, bc, pos_key);

    // value = x @ Wv^T + bv
    mma_gemm<0><<<dim3(DD/128, BL/128), 512, GSMEM>>>(bv, nullptr, nullptr);

    // chunked causal scan
    {
        dim3 grid(DD/128, NCH, BB);
        scan_partial<<<grid, 128>>>();
        scan_prefix<<<(BB*KK*DD)/256, 256>>>();
        scan_apply<<<grid, 128>>>();
    }

    // LayerNorm + fused bf16 conversion into A panels
    layernorm_conv<<<BL, 256>>>(ln_g, ln_b);

    // out = x + normed @ Wo^T + bo
    mma_gemm<1><<<dim3(DD/128, BL/128), 512, GSMEM>>>(bo, x, out);
}

// round 8
// speedup vs baseline: 1.7023x; 1.7023x over previous
#include <cuda_runtime.h>
#include <cuda_bf16.h>
#include <cuda_fp16.h>
#include <math.h>

// Problem constants
#define BB   4
#define LL   2048
#define DD   1024
#define KK   16
#define BL   (BB*LL)        // 8192 tokens
#define NCH  32             // scan chunks
#define LC   (LL/NCH)       // 64 tokens per chunk

// ---------------------------------------------------------------------------
// Scratch (no allocation allowed -> __device__ globals)
// ---------------------------------------------------------------------------
__device__ float g_value[BL*DD];            // 32 MB
__device__ float g_ret  [BL*DD];            // 32 MB (retrieved, pre-LN)
__device__ float g_ck   [BL*KK];
__device__ float g_cq   [BL*KK];
__device__ float g_S    [BB*NCH*KK*DD];     // 8 MB chunk states

// fp16 operand panels, chunk-major, swizzled (cell ^ (row&7)) layout.
// A panel: [chunk c][row t][8 cells x 16B]; 16 chunks * 8192 rows * 128B.
__device__ uint4 g_ahi[(16*8192*128)/16];   // 16 MB (x, later normed)
__device__ uint4 g_bhi[(16*1024*128)/16];   // 2 MB  (Wv)
__device__ uint4 g_bhi2[(16*1024*128)/16];  // 2 MB  (Wo)

// ---------------------------------------------------------------------------
// PTX helpers (base sm_90/sm_80 features only — target is plain sm_100!)
// ---------------------------------------------------------------------------
__device__ __forceinline__ unsigned smem_u32(const void* p) {
    unsigned a;
    asm("{ .reg .u64 t; cvta.to.shared.u64 t, %1; cvt.u32.u64 %0, t; }" : "=r"(a) : "l"(p));
    return a;
}

#define MBAR_INIT(addr, cnt) \
    asm volatile("mbarrier.init.shared.b64 [%0], %1;" :: "r"(addr), "r"(cnt) : "memory")
#define MBAR_INVAL(addr) \
    asm volatile("mbarrier.inval.shared.b64 [%0];" :: "r"(addr) : "memory")
#define MBAR_EXPECT_TX(addr, bytes) \
    asm volatile("mbarrier.arrive.expect_tx.shared.b64 _, [%0], %1;" :: "r"(addr), "r"(bytes) : "memory")
#define MBAR_ARRIVE(addr) \
    asm volatile("mbarrier.arrive.shared.b64 _, [%0];" :: "r"(addr) : "memory")

#define MBAR_WAIT(addr, par) do {                                              \
    unsigned _m = (addr), _p = (par), _d;                                      \
    asm volatile("{\n\t.reg .pred p;\n\t"                                      \
        "mbarrier.try_wait.parity.acquire.cta.shared::cta.b64 p, [%1], %2;\n\t"\
        "selp.b32 %0, 1, 0, p;\n\t}"                                           \
        : "=r"(_d) : "r"(_m), "r"(_p) : "memory");                             \
    if (!_d) {                                                                 \
        asm volatile("{\n\t.reg .pred P1;\n\t"                                 \
            "W%=:\n\t"                                                         \
            "mbarrier.try_wait.parity.acquire.cta.shared::cta.b64 P1, [%0], %1, 0x989680;\n\t" \
            "@P1 bra.uni D%=;\n\t"                                             \
            "bra.uni W%=;\n\t"                                                 \
            "D%=:\n\t}" :: "r"(_m), "r"(_p) : "memory");                       \
    }                                                                          \
} while (0)

#define CP_BULK(dst, src, bytes, mbar) \
    asm volatile("cp.async.bulk.shared::cluster.global.mbarrier::complete_tx::bytes [%0], [%1], %2, [%3];" \
        :: "r"(dst), "l"(src), "r"(bytes), "r"(mbar) : "memory")

#define FENCE_PROXY() asm volatile("fence.proxy.async.shared::cta;" ::: "memory")

#define LDSM_X4(r0, r1, r2, r3, addr) \
    asm volatile("ldmatrix.sync.aligned.m8n8.x4.shared.b16 {%0,%1,%2,%3}, [%4];" \
        : "=r"(r0), "=r"(r1), "=r"(r2), "=r"(r3) : "r"(addr))

__device__ __forceinline__ void mma16816h(float* d, const unsigned* a, const unsigned* b) {
    asm volatile("mma.sync.aligned.m16n8k16.row.col.f32.f16.f16.f32 "
        "{%0,%1,%2,%3}, {%4,%5,%6,%7}, {%8,%9}, {%0,%1,%2,%3};"
        : "+f"(d[0]), "+f"(d[1]), "+f"(d[2]), "+f"(d[3])
        : "r"(a[0]), "r"(a[1]), "r"(a[2]), "r"(a[3]), "r"(b[0]), "r"(b[1]));
}

// pack 2 floats -> fp16x2 bits
__device__ __forceinline__ unsigned pk2h(float x, float y) {
    __half2 h = __floats2half2_rn(x, y);
    return *reinterpret_cast<unsigned*>(&h);
}

// ---------------------------------------------------------------------------
// Kernel: conv_w — W (1024x1024 fp32) -> fp16 B panel (P=0: Wv, P=1: Wo)
// ---------------------------------------------------------------------------
template<int P>
__global__ __launch_bounds__(256)
void conv_w(const float* __restrict__ src)
{
    int id = blockIdx.x * 256 + threadIdx.x;     // 0 .. 1024*128-1
    int n = id >> 7;
    int cc = id & 127;
    int c = cc >> 3, cell = cc & 7;
    int k0 = c * 64 + cell * 8;

    const float4* s = (const float4*)(src + (size_t)n * DD + k0);
    float4 a = s[0], b = s[1];

    uint4 H = make_uint4(pk2h(a.x,a.y), pk2h(a.z,a.w), pk2h(b.x,b.y), pk2h(b.z,b.w));
    size_t off16 = ((size_t)c * DD + n) * 8 + (cell ^ (n & 7));
    if (P == 0) g_bhi[off16]  = H;
    else        g_bhi2[off16] = H;
}

// ---------------------------------------------------------------------------
// Kernel: mma_gemm — C[8192x1024] = A @ W^T (+bias, optionally +X residual)
// fp16 single-product (fp32 accum). 5-stage cp.async.bulk pipeline, scoped
// mbarrier flow control, register double-buffered ldmatrix.
// CTA tile 128x128, 16 warps (4x4), warp tile 32x32.
// MODE 0: C = g_value, B = Wv panel. MODE 1: C = Cout += X, B = Wo panel.
// ---------------------------------------------------------------------------
#define TILE_B  16384                   // one 128x64 fp16 tile
#define STG     (2*TILE_B)              // A, B = 32 KB
#define KBLK    16
#define NSTAGE  5
#define GSMEM   (1024 + NSTAGE*STG)     // 164864

template<int MODE>
__global__ __launch_bounds__(512, 1)
void mma_gemm(const float* __restrict__ bias, const float* __restrict__ X,
              float* __restrict__ Cout)
{
    extern __shared__ char smem[];
    unsigned sb = smem_u32(smem);
    int tid = threadIdx.x, lane = tid & 31, wid = tid >> 5;
    int wm = wid & 3, wn = wid >> 2;          // 4 x 4 warp grid, 32x32 tiles
    int bn = blockIdx.x * 128, bm = blockIdx.y * 128;
    float* C = (MODE == 0) ? g_value : Cout;

    // mbarriers: full[s] at sb+8+16s, cons[s] at sb+16+16s
    if (tid == 0) {
        #pragma unroll
        for (int s = 0; s < NSTAGE; ++s) {
            MBAR_INIT(sb + 8  + 16*s, 1);
            MBAR_INIT(sb + 16 + 16*s, 16);
        }
        FENCE_PROXY();
    }
    __syncthreads();

    const char* pA = (const char*)g_ahi;
    const char* pB = (MODE == 0) ? (const char*)g_bhi : (const char*)g_bhi2;

    auto issue = [&](int kb, int s) {
        unsigned st = sb + 1024 + s * STG;
        unsigned fm = sb + 8 + 16*s;
        size_t aoff = ((size_t)kb * BL + bm) * 128;
        size_t boff = ((size_t)kb * DD + bn) * 128;
        MBAR_EXPECT_TX(fm, STG);
        CP_BULK(st,          pA + aoff, TILE_B, fm);
        CP_BULK(st + TILE_B, pB + boff, TILE_B, fm);
    };
    if (tid == 0) {
        #pragma unroll
        for (int s = 0; s < NSTAGE - 1; ++s) issue(s, s);
    }

    float acc[2][4][4];
    #pragma unroll
    for (int i = 0; i < 2; ++i)
        #pragma unroll
        for (int j = 0; j < 4; ++j)
            #pragma unroll
            for (int q = 0; q < 4; ++q) acc[i][j][q] = 0.f;

    int rl = (lane & 7) + ((lane >> 3) & 1) * 8;
    int cs = lane >> 4;

    int rA[2], sA[2], rB[2], sB[2];
    #pragma unroll
    for (int i = 0; i < 2; ++i) { int r = wm*32 + i*16 + rl; rA[i] = r*128; sA[i] = r & 7; }
    #pragma unroll
    for (int j = 0; j < 2; ++j) { int r = wn*32 + j*16 + rl; rB[j] = r*128; sB[j] = r & 7; }

    // operand double buffers: A 8 regs, B 8 regs per buffer
    unsigned opA[2][8], opB[2][8];

    auto load_ops = [&](unsigned bA, unsigned bBp, int ks, unsigned* A, unsigned* B) {
        int cc = ks * 2 + cs;
        #pragma unroll
        for (int i = 0; i < 2; ++i) {
            unsigned off = rA[i] + ((cc ^ sA[i]) << 4);
            LDSM_X4(A[i*4+0], A[i*4+1], A[i*4+2], A[i*4+3], bA + off);
        }
        #pragma unroll
        for (int jp = 0; jp < 2; ++jp) {
            unsigned off = rB[jp] + ((cc ^ sB[jp]) << 4);
            unsigned r0, r1, r2, r3;
            LDSM_X4(r0, r1, r2, r3, bBp + off);
            B[jp*4+0] = r0; B[jp*4+1] = r2; B[jp*4+2] = r1; B[jp*4+3] = r3;
        }
    };

    auto do_mma = [&](const unsigned* A, const unsigned* B) {
        #pragma unroll
        for (int jp = 0; jp < 2; ++jp)
            #pragma unroll
            for (int i = 0; i < 2; ++i) {
                mma16816h(acc[i][jp*2+0], A + i*4, B + jp*4 + 0);
                mma16816h(acc[i][jp*2+1], A + i*4, B + jp*4 + 2);
            }
    };

    for (int kb = 0; kb < KBLK; ++kb) {
        int s  = kb % NSTAGE;
        int ph = (kb / NSTAGE) & 1;
        MBAR_WAIT(sb + 8 + 16*s, ph);
        unsigned st = sb + 1024 + s * STG;
        unsigned bA = st, bBp = st + TILE_B;

        load_ops(bA, bBp, 0, opA[0], opB[0]);
        #pragma unroll
        for (int ks = 0; ks < 4; ++ks) {
            int cur = ks & 1;
            if (ks < 3) load_ops(bA, bBp, ks + 1, opA[cur^1], opB[cur^1]);
            do_mma(opA[cur], opB[cur]);
        }

        if (lane == 0) MBAR_ARRIVE(sb + 16 + 16*s);
        if (tid == 0 && kb + NSTAGE - 1 < KBLK) {
            MBAR_WAIT(sb + 16 + 16*s, ph);
            issue(kb + NSTAGE - 1, (kb + NSTAGE - 1) % NSTAGE);
        }
    }

    // epilogue: warp writes its 32x32 sub-tile
    #pragma unroll
    for (int i = 0; i < 2; ++i) {
        int r0 = bm + wm*32 + i*16 + (lane >> 2);
        #pragma unroll
        for (int j = 0; j < 4; ++j) {
            int col = bn + wn*32 + j*8 + (lane & 3)*2;
            float2 b2 = *(const float2*)(bias + col);
            float2 v0 = make_float2(acc[i][j][0] + b2.x, acc[i][j][1] + b2.y);
            float2 v1 = make_float2(acc[i][j][2] + b2.x, acc[i][j][3] + b2.y);
            if (MODE == 1) {
                float2 x0 = *(const float2*)(X + (size_t)r0*DD + col);
                float2 x1 = *(const float2*)(X + (size_t)(r0+8)*DD + col);
                v0.x += x0.x; v0.y += x0.y;
                v1.x += x1.x; v1.y += x1.y;
            }
            *(float2*)(C + (size_t)r0*DD + col)     = v0;
            *(float2*)(C + (size_t)(r0+8)*DD + col) = v1;
        }
    }

    __syncthreads();
    if (tid == 0) {
        #pragma unroll
        for (int s = 0; s < NSTAGE; ++s) {
            MBAR_INVAL(sb + 8  + 16*s);
            MBAR_INVAL(sb + 16 + 16*s);
        }
    }
}

// ---------------------------------------------------------------------------
// Kernel: proj — content key/query + combiner for 8 tokens per block,
// FUSED with x -> fp16 A-panel conversion (reads x once).
// 1024 blocks x 256 threads.
// ---------------------------------------------------------------------------
#define PT 8
__global__ __launch_bounds__(256)
void proj_kernel(const float* __restrict__ x,
                 const float* __restrict__ Wck, const float* __restrict__ bck,
                 const float* __restrict__ Wcq, const float* __restrict__ bcq,
                 const float* __restrict__ Wc,  const float* __restrict__ bc,
                 const float* __restrict__ pos_key)
{
    int t0   = blockIdx.x * PT;
    int tid  = threadIdx.x;
    int lane = tid & 31;
    int warp = tid >> 5;

    __shared__ float xs[PT][DD];
    __shared__ float dots[2][PT][16];
    __shared__ float pos_s[PT][16];

    #pragma unroll
    for (int i = tid; i < PT*DD/4; i += 256)
        ((float4*)&xs[0][0])[i] = ((const float4*)(x + (size_t)t0*DD))[i];
    if (tid < PT*16) {
        int tt = tid >> 4, k = tid & 15;
        int l = (t0 + tt) & (LL-1);
        pos_s[tt][k] = pos_key[l*KK + k];
    }
    __syncthreads();

    // --- fused conv: emit fp16 panel rows ---
    {
        int tt   = tid >> 5;              // row within block (0..7)
        int t    = t0 + tt;
        int cell = lane & 7;
        #pragma unroll
        for (int q = 0; q < 4; ++q) {
            int c  = (lane >> 3) + q*4;   // chunk 0..15
            int k0 = c*64 + cell*8;
            const float* v = &xs[tt][k0];
            uint4 H = make_uint4(pk2h(v[0],v[1]), pk2h(v[2],v[3]),
                                 pk2h(v[4],v[5]), pk2h(v[6],v[7]));
            size_t off16 = ((size_t)c * BL + t) * 8 + (cell ^ (t & 7));
            g_ahi[off16] = H;
        }
    }

    // --- 32 dot products; each warp does 4 (sequential — keeps regs low) ---
    #pragma unroll 1
    for (int oo = 0; oo < 4; ++oo) {
        int o = warp + oo*8;
        const float* W = (o < 16) ? (Wck + (size_t)o*DD) : (Wcq + (size_t)(o-16)*DD);
        float bias_o   = (o < 16) ? bck[o] : bcq[o-16];
        float wreg[32];
        #pragma unroll
        for (int i = 0; i < 32; ++i) wreg[i] = W[lane + 32*i];
        #pragma unroll
        for (int t = 0; t < PT; ++t) {
            float s = 0.f;
            #pragma unroll
            for (int i = 0; i < 32; ++i) s += wreg[i] * xs[t][lane + 32*i];
            #pragma unroll
            for (int off = 16; off; off >>= 1)
                s += __shfl_xor_sync(0xffffffffu, s, off);
            if (lane == 0)
                dots[o >> 4][t][o & 15] = s + bias_o;
        }
    }
    __syncthreads();

    // --- normalize + combiner + normalize ---
    {
        int t    = warp;
        int path = lane >> 4;
        int l16  = lane & 15;

        float v = dots[path][t][l16];
        float ss = v*v;
        #pragma unroll
        for (int off = 8; off; off >>= 1)
            ss += __shfl_xor_sync(0xffffffffu, ss, off, 16);
        float cnv = v / fmaxf(sqrtf(ss), 1e-12f);

        float s = bc[l16];
        #pragma unroll
        for (int j = 0; j < 16; ++j) {
            float cj = __shfl_sync(0xffffffffu, cnv, j, 16);
            s += Wc[l16*32 + j]      * pos_s[t][j];
            s += Wc[l16*32 + 16 + j] * cj;
        }
        s = tanhf(s);
        float sq = s*s;
        #pragma unroll
        for (int off = 8; off; off >>= 1)
            sq += __shfl_xor_sync(0xffffffffu, sq, off, 16);
        float outv = s / fmaxf(sqrtf(sq), 1e-12f);
        float* dst = (path == 0) ? g_ck : g_cq;
        dst[(t0 + t)*KK + l16] = outv;
    }
}

// ---------------------------------------------------------------------------
// Kernel: per-chunk partial state  S[b,c,k,d] = sum_{t in chunk} v[t,d]*ck[t,k]
// ---------------------------------------------------------------------------
__global__ __launch_bounds__(128)
void scan_partial()
{
    int d = blockIdx.x * 128 + threadIdx.x;
    int c = blockIdx.y;
    int b = blockIdx.z;
    __shared__ float cks[LC*KK];

    int base_t = b*LL + c*LC;
    for (int i = threadIdx.x; i < LC*KK; i += 128)
        cks[i] = g_ck[base_t*KK + i];
    __syncthreads();

    float st[KK];
    #pragma unroll
    for (int k = 0; k < KK; ++k) st[k] = 0.f;

    const float* vp = g_value + (size_t)base_t*DD + d;
    for (int t = 0; t < LC; ++t) {
        float v = vp[(size_t)t*DD];
        #pragma unroll
        for (int k = 0; k < KK; ++k) st[k] += v * cks[t*KK + k];
    }
    float* Sp = g_S + ((size_t)(b*NCH + c)*KK)*DD + d;
    #pragma unroll
    for (int k = 0; k < KK; ++k) Sp[(size_t)k*DD] = st[k];
}

// ---------------------------------------------------------------------------
// Kernel: exclusive prefix over chunks — batched loads for MLP
// ---------------------------------------------------------------------------
__global__ __launch_bounds__(256)
void scan_prefix()
{
    int id  = blockIdx.x * 256 + threadIdx.x;   // 0 .. B*K*D-1
    int b   = id >> 14;
    int rem = id & 16383;
    float* base = g_S + (size_t)b*NCH*KK*DD + rem;

    float v[NCH];
    #pragma unroll
    for (int c = 0; c < NCH; ++c)
        v[c] = base[(size_t)c*KK*DD];
    float run = 0.f;
    #pragma unroll
    for (int c = 0; c < NCH; ++c) {
        float t = v[c];
        base[(size_t)c*KK*DD] = run;
        run += t;
    }
}

// ---------------------------------------------------------------------------
// Kernel: apply scan within chunk -> retrieved (scaled 1/sqrt K) into g_ret
// ---------------------------------------------------------------------------
__global__ __launch_bounds__(128)
void scan_apply()
{
    int d = blockIdx.x * 128 + threadIdx.x;
    int c = blockIdx.y;
    int b = blockIdx.z;
    __shared__ float cks[LC*KK];
    __shared__ float cqs[LC*KK];

    int base_t = b*LL + c*LC;
    for (int i = threadIdx.x; i < LC*KK; i += 128) {
        cks[i] = g_ck[base_t*KK + i];
        cqs[i] = g_cq[base_t*KK + i];
    }
    __syncthreads();

    float st[KK];
    const float* Sp = g_S + ((size_t)(b*NCH + c)*KK)*DD + d;
    #pragma unroll
    for (int k = 0; k < KK; ++k) st[k] = Sp[(size_t)k*DD];

    const float* vp = g_value + (size_t)base_t*DD + d;
    float*       rp = g_ret   + (size_t)base_t*DD + d;
    for (int t = 0; t < LC; ++t) {
        float v = vp[(size_t)t*DD];
        float acc = 0.f;
        #pragma unroll
        for (int k = 0; k < KK; ++k) {
            st[k] += v * cks[t*KK + k];
            acc   += cqs[t*KK + k] * st[k];
        }
        rp[(size_t)t*DD] = acc * 0.25f;
    }
}

// ---------------------------------------------------------------------------
// Kernel: LayerNorm on g_ret, fused fp16 panel output (for mma_gemm<1>)
// ---------------------------------------------------------------------------
__global__ __launch_bounds__(256)
void layernorm_conv(const float* __restrict__ gam, const float* __restrict__ bet)
{
    int t = blockIdx.x;
    const float* row = g_ret + (size_t)t*DD;
    __shared__ float sh[DD];
    __shared__ float ws[8], wq[8];
    __shared__ float s_mean, s_rstd;

    int tid  = threadIdx.x;
    int lane = tid & 31;
    int wid  = tid >> 5;

    float4 v = ((const float4*)row)[tid];
    ((float4*)sh)[tid] = v;
    float s = v.x + v.y + v.z + v.w;
    float q = v.x*v.x + v.y*v.y + v.z*v.z + v.w*v.w;
    #pragma unroll
    for (int off = 16; off; off >>= 1) {
        s += __shfl_xor_sync(0xffffffffu, s, off);
        q += __shfl_xor_sync(0xffffffffu, q, off);
    }
    if (lane == 0) { ws[wid] = s; wq[wid] = q; }
    __syncthreads();
    if (tid == 0) {
        float S = 0.f, Q = 0.f;
        #pragma unroll
        for (int i = 0; i < 8; ++i) { S += ws[i]; Q += wq[i]; }
        float m   = S / (float)DD;
        float var = Q / (float)DD - m*m;
        s_mean = m;
        s_rstd = rsqrtf(var + 1e-5f);
    }
    __syncthreads();
    float m = s_mean, r = s_rstd;

    int d0 = tid * 4;
    float nv[4];
    #pragma unroll
    for (int i = 0; i < 4; ++i) {
        int d = d0 + i;
        nv[i] = (sh[d] - m) * r * gam[d] + bet[d];
    }
    int c8    = d0 >> 6;
    int inrow = ((d0 & 63) * 2) ^ ((t & 7) << 4);
    size_t byteoff = ((size_t)c8 * BL + t) * 128 + inrow;
    *(uint2*)((char*)g_ahi + byteoff) = make_uint2(pk2h(nv[0],nv[1]), pk2h(nv[2],nv[3]));
}

// ---------------------------------------------------------------------------
extern "C" void kernel_launch(void* const* d_in, const int* in_sizes, int n_in,
                              void* d_out, int out_size)
{
    const float* x       = (const float*)d_in[0];
    const float* Wv      = (const float*)d_in[1];
    const float* bv      = (const float*)d_in[2];
    const float* Wck     = (const float*)d_in[3];
    const float* bck     = (const float*)d_in[4];
    const float* Wc      = (const float*)d_in[5];
    const float* bc      = (const float*)d_in[6];
    const float* Wcq     = (const float*)d_in[7];
    const float* bcq     = (const float*)d_in[8];
    const float* ln_g    = (const float*)d_in[9];
    const float* ln_b    = (const float*)d_in[10];
    const float* Wo      = (const float*)d_in[11];
    const float* bo      = (const float*)d_in[12];
    const float* pos_key = (const float*)d_in[13];
    float* out = (float*)d_out;

    cudaFuncSetAttribute(mma_gemm<0>, cudaFuncAttributeMaxDynamicSharedMemorySize, GSMEM);
    cudaFuncSetAttribute(mma_gemm<1>, cudaFuncAttributeMaxDynamicSharedMemorySize, GSMEM);

    // weight panels (off critical path)
    conv_w<0><<<(DD*128)/256, 256>>>(Wv);
    conv_w<1><<<(DD*128)/256, 256>>>(Wo);

    // proj + fused x->panel conversion
    proj_kernel<<<BL/PT, 256>>>(x, Wck, bck, Wcq, bcq, Wc, bc, pos_key);

    // value = x @ Wv^T + bv
    mma_gemm<0><<<dim3(DD/128, BL/128), 512, GSMEM>>>(bv, nullptr, nullptr);

    // chunked causal scan
    {
        dim3 grid(DD/128, NCH, BB);
        scan_partial<<<grid, 128>>>();
        scan_prefix<<<(BB*KK*DD)/256, 256>>>();
        scan_apply<<<grid, 128>>>();
    }

    // LayerNorm + fused fp16 conversion into A panel
    layernorm_conv<<<BL, 256>>>(ln_g, ln_b);

    // out = x + normed @ Wo^T + bo
    mma_gemm<1><<<dim3(DD/128, BL/128), 512, GSMEM>>>(bo, x, out);
}